// round 2
// baseline (speedup 1.0000x reference)
#include <cuda_runtime.h>

#define NN 100000
#define NE 3200000
#define INF 512
#define HID 32

// ---- scratch (static device globals; no allocation) ----
__device__ int   g_deg[NN];
__device__ int   g_rowstart[NN + 1];
__device__ int   g_cursor[NN];
__device__ float g_dinv[NN];
__device__ int   g_csr[NE];
__device__ __align__(16) float g_hs[(size_t)NN * HID];   // (x @ W) * dinv  per node
__device__ __align__(16) float g_x[(size_t)NN * HID];    // activations x1/x2/x3

// ---------------- preprocessing ----------------

__global__ void zero_deg_kernel() {
    int i = blockIdx.x * blockDim.x + threadIdx.x;
    if (i < NN) g_deg[i] = 0;
}

__global__ void deg_kernel(const int* __restrict__ edge) {
    int e = blockIdx.x * blockDim.x + threadIdx.x;
    if (e < NE) {
        int d = edge[NE + e];   // dst row (int32)
        if ((unsigned)d < NN) atomicAdd(&g_deg[d], 1);
    }
}

// single-block exclusive scan of g_deg -> g_rowstart / g_cursor, plus dinv
__global__ void scan_kernel() {
    __shared__ int warpsums[32];
    __shared__ int s_carry;
    int tid = threadIdx.x;           // 1024 threads
    int lane = tid & 31, wid = tid >> 5;
    if (tid == 0) s_carry = 0;
    __syncthreads();
    for (int base = 0; base < NN; base += 4096) {
        int i0 = base + tid * 4;
        int v0 = (i0 + 0 < NN) ? g_deg[i0 + 0] : 0;
        int v1 = (i0 + 1 < NN) ? g_deg[i0 + 1] : 0;
        int v2 = (i0 + 2 < NN) ? g_deg[i0 + 2] : 0;
        int v3 = (i0 + 3 < NN) ? g_deg[i0 + 3] : 0;
        int tsum = v0 + v1 + v2 + v3;
        int incl = tsum;
        #pragma unroll
        for (int o = 1; o < 32; o <<= 1) {
            int t = __shfl_up_sync(0xffffffffu, incl, o);
            if (lane >= o) incl += t;
        }
        if (lane == 31) warpsums[wid] = incl;
        __syncthreads();
        if (wid == 0) {
            int ws = warpsums[lane];
            #pragma unroll
            for (int o = 1; o < 32; o <<= 1) {
                int t = __shfl_up_sync(0xffffffffu, ws, o);
                if (lane >= o) ws += t;
            }
            warpsums[lane] = ws;
        }
        __syncthreads();
        int carry = s_carry;
        int run = carry + incl - tsum + ((wid > 0) ? warpsums[wid - 1] : 0);
        if (i0 + 0 < NN) { g_rowstart[i0 + 0] = run; g_cursor[i0 + 0] = run; g_dinv[i0 + 0] = rsqrtf((float)v0 + 1.0f); run += v0; }
        if (i0 + 1 < NN) { g_rowstart[i0 + 1] = run; g_cursor[i0 + 1] = run; g_dinv[i0 + 1] = rsqrtf((float)v1 + 1.0f); run += v1; }
        if (i0 + 2 < NN) { g_rowstart[i0 + 2] = run; g_cursor[i0 + 2] = run; g_dinv[i0 + 2] = rsqrtf((float)v2 + 1.0f); run += v2; }
        if (i0 + 3 < NN) { g_rowstart[i0 + 3] = run; g_cursor[i0 + 3] = run; g_dinv[i0 + 3] = rsqrtf((float)v3 + 1.0f); run += v3; }
        __syncthreads();
        if (tid == 0) s_carry = carry + warpsums[31];
        __syncthreads();
    }
    if (tid == 0) g_rowstart[NN] = s_carry;
}

__global__ void scatter_kernel(const int* __restrict__ edge) {
    int e = blockIdx.x * blockDim.x + threadIdx.x;
    if (e < NE) {
        int s = edge[e];
        int d = edge[NE + e];
        if ((unsigned)d < NN && (unsigned)s < NN) {
            int p = atomicAdd(&g_cursor[d], 1);
            g_csr[p] = s;
        }
    }
}

// ---------------- GEMM1: hs = (x0 @ W1) * dinv  [100000x512 @ 512x32] ----------------
// 64x32 block tile, BK=32, 128 threads, 4x4 thread tile. fp32 FFMA.
__global__ __launch_bounds__(128) void gemm1_kernel(
    const float* __restrict__ x0, const float* __restrict__ W) {
    __shared__ float Xs[64][33];
    __shared__ __align__(16) float Ws[32][32];
    int tid = threadIdx.x;
    int ty = tid >> 3;           // 0..15 (row group of 4)
    int tx = tid & 7;            // 0..7  (col group of 4)
    int row0 = blockIdx.x * 64;
    float acc[4][4];
    #pragma unroll
    for (int i = 0; i < 4; i++)
        #pragma unroll
        for (int j = 0; j < 4; j++) acc[i][j] = 0.0f;

    for (int kc = 0; kc < INF; kc += 32) {
        #pragma unroll
        for (int j = 0; j < 8; j++) {
            int i = tid + j * 128;          // 0..1023
            Ws[i >> 5][i & 31] = W[(kc + (i >> 5)) * HID + (i & 31)];
        }
        #pragma unroll
        for (int j = 0; j < 4; j++) {
            int i = tid + j * 128;          // 0..511
            int r = i >> 3;                 // 0..63
            int kv = (i & 7) << 2;          // 0,4,...,28
            int row = row0 + r;
            float4 v = make_float4(0.f, 0.f, 0.f, 0.f);
            if (row < NN) v = *(const float4*)&x0[(size_t)row * INF + kc + kv];
            Xs[r][kv + 0] = v.x; Xs[r][kv + 1] = v.y;
            Xs[r][kv + 2] = v.z; Xs[r][kv + 3] = v.w;
        }
        __syncthreads();
        #pragma unroll
        for (int k = 0; k < 32; k++) {
            float a0 = Xs[ty * 4 + 0][k];
            float a1 = Xs[ty * 4 + 1][k];
            float a2 = Xs[ty * 4 + 2][k];
            float a3 = Xs[ty * 4 + 3][k];
            float4 b = *(const float4*)&Ws[k][tx * 4];
            acc[0][0] += a0 * b.x; acc[0][1] += a0 * b.y; acc[0][2] += a0 * b.z; acc[0][3] += a0 * b.w;
            acc[1][0] += a1 * b.x; acc[1][1] += a1 * b.y; acc[1][2] += a1 * b.z; acc[1][3] += a1 * b.w;
            acc[2][0] += a2 * b.x; acc[2][1] += a2 * b.y; acc[2][2] += a2 * b.z; acc[2][3] += a2 * b.w;
            acc[3][0] += a3 * b.x; acc[3][1] += a3 * b.y; acc[3][2] += a3 * b.z; acc[3][3] += a3 * b.w;
        }
        __syncthreads();
    }
    #pragma unroll
    for (int i = 0; i < 4; i++) {
        int row = row0 + ty * 4 + i;
        if (row < NN) {
            float dv = g_dinv[row];
            float4 o = make_float4(acc[i][0] * dv, acc[i][1] * dv, acc[i][2] * dv, acc[i][3] * dv);
            *(float4*)&g_hs[(size_t)row * HID + tx * 4] = o;
        }
    }
}

// ---------------- small GEMM: hs = (g_x @ W) * dinv   [N x 32 @ 32 x 32] ----------------
__global__ __launch_bounds__(256) void gemm32_kernel(const float* __restrict__ W) {
    __shared__ float Ws[HID * HID];
    int tid = threadIdx.x;          // 256
    #pragma unroll
    for (int i = tid; i < HID * HID; i += 256) Ws[i] = W[i];
    __syncthreads();
    int lane = tid & 31;
    int gw = (blockIdx.x * blockDim.x + tid) >> 5;   // warp id
    int row0 = gw * 4;
    #pragma unroll
    for (int r = 0; r < 4; r++) {
        int row = row0 + r;
        if (row >= NN) return;      // warp-uniform
        float xv = g_x[(size_t)row * HID + lane];
        float acc = 0.0f;
        #pragma unroll
        for (int k = 0; k < HID; k++)
            acc += __shfl_sync(0xffffffffu, xv, k) * Ws[k * HID + lane];
        g_hs[(size_t)row * HID + lane] = acc * g_dinv[row];
    }
}

// ---------------- aggregate: g_x = relu(dinv_i * (sum_{j->i} hs_j + hs_i) + b) ----------------
__global__ __launch_bounds__(256) void agg_kernel(const float* __restrict__ bias) {
    int gw = (blockIdx.x * blockDim.x + threadIdx.x) >> 5;   // node = warp
    int lane = threadIdx.x & 31;
    if (gw >= NN) return;
    int r0 = g_rowstart[gw];
    int r1 = g_rowstart[gw + 1];
    float acc  = g_hs[(size_t)gw * HID + lane];   // self term (already *dinv)
    float acc2 = 0.0f;
    int e = r0;
    for (; e + 32 <= r1; e += 32) {
        int idx = g_csr[e + lane];
        #pragma unroll
        for (int j = 0; j < 32; j += 2) {
            int s0 = __shfl_sync(0xffffffffu, idx, j);
            int s1 = __shfl_sync(0xffffffffu, idx, j + 1);
            acc  += g_hs[(size_t)s0 * HID + lane];
            acc2 += g_hs[(size_t)s1 * HID + lane];
        }
    }
    int rem = r1 - e;
    int idx = (lane < rem) ? g_csr[e + lane] : 0;
    for (int j = 0; j < rem; j++) {
        int s = __shfl_sync(0xffffffffu, idx, j);
        acc += g_hs[(size_t)s * HID + lane];
    }
    float v = g_dinv[gw] * (acc + acc2) + bias[lane];
    g_x[(size_t)gw * HID + lane] = fmaxf(v, 0.0f);
}

// ---------------- head: out = relu(x3 @ lin1 + b1) @ lin2 + b2 ----------------
__global__ __launch_bounds__(256) void mlp_kernel(
    const float* __restrict__ W1, const float* __restrict__ b1,
    const float* __restrict__ W2, const float* __restrict__ b2,
    float* __restrict__ out) {
    __shared__ float sW1[32 * 16];
    __shared__ float sW2[16 * 10];
    __shared__ float sb1[16];
    __shared__ float sb2[10];
    int tid = threadIdx.x;   // 256
    #pragma unroll
    for (int i = tid; i < 512; i += 256) sW1[i] = W1[i];
    if (tid < 160) sW2[tid] = W2[tid];
    if (tid < 16)  sb1[tid] = b1[tid];
    if (tid < 10)  sb2[tid] = b2[tid];
    __syncthreads();
    int lane = tid & 31;
    int row = (blockIdx.x * blockDim.x + tid) >> 5;
    if (row >= NN) return;
    float xv = g_x[(size_t)row * HID + lane];
    int c = lane & 15;
    float t = sb1[c];
    #pragma unroll
    for (int k = 0; k < 32; k++)
        t += __shfl_sync(0xffffffffu, xv, k) * sW1[k * 16 + c];
    t = fmaxf(t, 0.0f);
    int oc = (lane < 10) ? lane : 0;
    float o = sb2[oc];
    #pragma unroll
    for (int c2 = 0; c2 < 16; c2++) {
        float tv = __shfl_sync(0xffffffffu, t, c2);   // lanes 0..15 hold layer-1 outputs
        o += tv * sW2[c2 * 10 + oc];
    }
    if (lane < 10) out[(size_t)row * 10 + lane] = o;
}

// ---------------- launch ----------------

extern "C" void kernel_launch(void* const* d_in, const int* in_sizes, int n_in,
                              void* d_out, int out_size) {
    (void)in_sizes; (void)n_in; (void)out_size;
    const float* x0   = (const float*)d_in[0];
    const int*   edge = (const int*)d_in[1];   // int32: JAX x64 disabled -> int64 decays to int32
    // d_in[2] = batch (unused)
    const float* W1  = (const float*)d_in[3];
    const float* b1  = (const float*)d_in[4];
    const float* W2  = (const float*)d_in[5];
    const float* b2  = (const float*)d_in[6];
    const float* W3  = (const float*)d_in[7];
    const float* b3  = (const float*)d_in[8];
    const float* l1W = (const float*)d_in[9];
    const float* l1b = (const float*)d_in[10];
    const float* l2W = (const float*)d_in[11];
    const float* l2b = (const float*)d_in[12];
    float* out = (float*)d_out;

    // CSR build (reused by all 3 layers)
    zero_deg_kernel<<<(NN + 255) / 256, 256>>>();
    deg_kernel<<<(NE + 255) / 256, 256>>>(edge);
    scan_kernel<<<1, 1024>>>();
    scatter_kernel<<<(NE + 255) / 256, 256>>>(edge);

    // layer 1
    gemm1_kernel<<<(NN + 63) / 64, 128>>>(x0, W1);
    agg_kernel<<<12500, 256>>>(b1);     // 100000 warps, 8 warps/block
    // layer 2
    gemm32_kernel<<<3125, 256>>>(W2);   // 25000 warps * 4 rows
    agg_kernel<<<12500, 256>>>(b2);
    // layer 3
    gemm32_kernel<<<3125, 256>>>(W3);
    agg_kernel<<<12500, 256>>>(b3);
    // head
    mlp_kernel<<<12500, 256>>>(l1W, l1b, l2W, l2b, out);
}

// round 3
// speedup vs baseline: 1.1915x; 1.1915x over previous
#include <cuda_runtime.h>

#define NN 100000
#define NE 3200000
#define INF 512
#define HID 32
#define NBLK_SCAN 98   // ceil(NN/1024)

// ---- scratch (static device globals; no allocation) ----
__device__ int   g_deg[NN];
__device__ int   g_rowstart[NN + 1];
__device__ int   g_cursor[NN];
__device__ float g_dinv[NN];
__device__ int   g_csr[NE];
__device__ int   g_bsum[NBLK_SCAN];
__device__ int   g_boff[NBLK_SCAN];
__device__ __align__(16) float g_hsA[(size_t)NN * HID];
__device__ __align__(16) float g_hsB[(size_t)NN * HID];

// ---------------- preprocessing ----------------

__global__ void zero_deg_kernel() {
    int i = blockIdx.x * blockDim.x + threadIdx.x;
    if (i < NN) g_deg[i] = 0;
}

__global__ void deg_kernel(const int* __restrict__ edge) {
    int e4 = blockIdx.x * blockDim.x + threadIdx.x;   // 800000 groups of 4
    if (e4 < NE / 4) {
        int4 d = ((const int4*)(edge + NE))[e4];
        if ((unsigned)d.x < NN) atomicAdd(&g_deg[d.x], 1);
        if ((unsigned)d.y < NN) atomicAdd(&g_deg[d.y], 1);
        if ((unsigned)d.z < NN) atomicAdd(&g_deg[d.z], 1);
        if ((unsigned)d.w < NN) atomicAdd(&g_deg[d.w], 1);
    }
}

// scan phase 1: per-block (1024 elems) sum
__global__ __launch_bounds__(256) void scan1_kernel() {
    __shared__ int wsum[8];
    int tid = threadIdx.x, lane = tid & 31, wid = tid >> 5;
    int i0 = blockIdx.x * 1024 + tid * 4;
    int s = 0;
    if (i0 + 3 < NN) {
        int4 v = *(const int4*)&g_deg[i0];
        s = v.x + v.y + v.z + v.w;
    } else {
        for (int j = 0; j < 4; j++) if (i0 + j < NN) s += g_deg[i0 + j];
    }
    #pragma unroll
    for (int o = 16; o > 0; o >>= 1) s += __shfl_xor_sync(0xffffffffu, s, o);
    if (lane == 0) wsum[wid] = s;
    __syncthreads();
    if (tid == 0) {
        int t = 0;
        #pragma unroll
        for (int w = 0; w < 8; w++) t += wsum[w];
        g_bsum[blockIdx.x] = t;
    }
}

// scan phase 2: scan the 98 block sums (single small block)
__global__ __launch_bounds__(128) void scan2_kernel() {
    __shared__ int wsum[4];
    int tid = threadIdx.x, lane = tid & 31, wid = tid >> 5;
    int v = (tid < NBLK_SCAN) ? g_bsum[tid] : 0;
    int incl = v;
    #pragma unroll
    for (int o = 1; o < 32; o <<= 1) {
        int t = __shfl_up_sync(0xffffffffu, incl, o);
        if (lane >= o) incl += t;
    }
    if (lane == 31) wsum[wid] = incl;
    __syncthreads();
    int woff = 0;
    for (int w = 0; w < wid; w++) woff += wsum[w];
    int excl = woff + incl - v;
    if (tid < NBLK_SCAN) g_boff[tid] = excl;
    if (tid == NBLK_SCAN - 1) g_rowstart[NN] = excl + v;
}

// scan phase 3: local scan + offset, write rowstart/cursor/dinv
__global__ __launch_bounds__(256) void scan3_kernel() {
    __shared__ int wsum[8];
    int tid = threadIdx.x, lane = tid & 31, wid = tid >> 5;
    int i0 = blockIdx.x * 1024 + tid * 4;
    int v0 = 0, v1 = 0, v2 = 0, v3 = 0;
    if (i0 + 3 < NN) {
        int4 v = *(const int4*)&g_deg[i0];
        v0 = v.x; v1 = v.y; v2 = v.z; v3 = v.w;
    } else {
        if (i0 + 0 < NN) v0 = g_deg[i0 + 0];
        if (i0 + 1 < NN) v1 = g_deg[i0 + 1];
        if (i0 + 2 < NN) v2 = g_deg[i0 + 2];
        if (i0 + 3 < NN) v3 = g_deg[i0 + 3];
    }
    int tsum = v0 + v1 + v2 + v3;
    int incl = tsum;
    #pragma unroll
    for (int o = 1; o < 32; o <<= 1) {
        int t = __shfl_up_sync(0xffffffffu, incl, o);
        if (lane >= o) incl += t;
    }
    if (lane == 31) wsum[wid] = incl;
    __syncthreads();
    int woff = 0;
    for (int w = 0; w < wid; w++) woff += wsum[w];
    int run = g_boff[blockIdx.x] + woff + incl - tsum;
    if (i0 + 0 < NN) { g_rowstart[i0 + 0] = run; g_cursor[i0 + 0] = run; g_dinv[i0 + 0] = rsqrtf((float)v0 + 1.0f); run += v0; }
    if (i0 + 1 < NN) { g_rowstart[i0 + 1] = run; g_cursor[i0 + 1] = run; g_dinv[i0 + 1] = rsqrtf((float)v1 + 1.0f); run += v1; }
    if (i0 + 2 < NN) { g_rowstart[i0 + 2] = run; g_cursor[i0 + 2] = run; g_dinv[i0 + 2] = rsqrtf((float)v2 + 1.0f); run += v2; }
    if (i0 + 3 < NN) { g_rowstart[i0 + 3] = run; g_cursor[i0 + 3] = run; g_dinv[i0 + 3] = rsqrtf((float)v3 + 1.0f); run += v3; }
}

__global__ void scatter_kernel(const int* __restrict__ edge) {
    int e4 = blockIdx.x * blockDim.x + threadIdx.x;
    if (e4 < NE / 4) {
        int4 s = ((const int4*)edge)[e4];
        int4 d = ((const int4*)(edge + NE))[e4];
        if ((unsigned)d.x < NN && (unsigned)s.x < NN) g_csr[atomicAdd(&g_cursor[d.x], 1)] = s.x;
        if ((unsigned)d.y < NN && (unsigned)s.y < NN) g_csr[atomicAdd(&g_cursor[d.y], 1)] = s.y;
        if ((unsigned)d.z < NN && (unsigned)s.z < NN) g_csr[atomicAdd(&g_cursor[d.z], 1)] = s.z;
        if ((unsigned)d.w < NN && (unsigned)s.w < NN) g_csr[atomicAdd(&g_cursor[d.w], 1)] = s.w;
    }
}

// ---------------- GEMM1: hsA = (x0 @ W1) * dinv  [100000x512 @ 512x32] ----------------
// FFMA2 (fma.rn.f32x2) packed over even/odd k. 64x32 block tile, BK=32,
// 128 threads, 4x4 thread tile, acc = 16 packed f32x2.
#define XS_STRIDE 36
#define WT_STRIDE 38
__global__ __launch_bounds__(128) void gemm1_kernel(
    const float* __restrict__ x0, const float* __restrict__ W) {
    __shared__ __align__(16) float Xs[64 * XS_STRIDE];   // [row][k]
    __shared__ __align__(16) float Wt[32 * WT_STRIDE];   // [col][k] (transposed)
    int tid = threadIdx.x;
    int ty = tid >> 3;           // 0..15 -> rows ty*4..+3
    int tx = tid & 7;            // 0..7  -> cols tx*4..+3
    int row0 = blockIdx.x * 64;

    unsigned long long acc[4][4];
    #pragma unroll
    for (int i = 0; i < 4; i++)
        #pragma unroll
        for (int j = 0; j < 4; j++) acc[i][j] = 0ull;

    for (int kc = 0; kc < INF; kc += 32) {
        // W tile transposed: Wt[c][k] = W[kc+k][c]
        #pragma unroll
        for (int t = 0; t < 8; t++) {
            int lin = tid + t * 128;         // 0..1023
            int k = lin >> 5, c = lin & 31;
            Wt[c * WT_STRIDE + k] = W[(kc + k) * HID + c];
        }
        // X tile row-major
        #pragma unroll
        for (int t = 0; t < 4; t++) {
            int lin = tid + t * 128;         // 0..511
            int r = lin >> 3;
            int kv = (lin & 7) << 2;
            int row = row0 + r;
            if (row >= NN) row = NN - 1;     // clamp (safe, store guarded)
            float4 v = *(const float4*)&x0[(size_t)row * INF + kc + kv];
            *(float4*)&Xs[r * XS_STRIDE + kv] = v;
        }
        __syncthreads();
        #pragma unroll
        for (int kp = 0; kp < 16; kp++) {    // k-pair: k=2kp,2kp+1
            unsigned long long a[4], b[4];
            #pragma unroll
            for (int i = 0; i < 4; i++)
                a[i] = *(const unsigned long long*)&Xs[(ty * 4 + i) * XS_STRIDE + 2 * kp];
            #pragma unroll
            for (int j = 0; j < 4; j++)
                b[j] = *(const unsigned long long*)&Wt[(tx * 4 + j) * WT_STRIDE + 2 * kp];
            #pragma unroll
            for (int i = 0; i < 4; i++)
                #pragma unroll
                for (int j = 0; j < 4; j++)
                    asm("fma.rn.f32x2 %0, %1, %2, %0;"
                        : "+l"(acc[i][j]) : "l"(a[i]), "l"(b[j]));
        }
        __syncthreads();
    }
    #pragma unroll
    for (int i = 0; i < 4; i++) {
        int row = row0 + ty * 4 + i;
        if (row < NN) {
            float dv = g_dinv[row];
            float4 o;
            float* op = (float*)&o;
            #pragma unroll
            for (int j = 0; j < 4; j++) {
                unsigned long long p = acc[i][j];
                float lo = __uint_as_float((unsigned)(p & 0xffffffffu));
                float hi = __uint_as_float((unsigned)(p >> 32));
                op[j] = (lo + hi) * dv;
            }
            *(float4*)&g_hsA[(size_t)row * HID + tx * 4] = o;
        }
    }
}

// ---------------- fused aggregate + next linear ----------------
// x_i = relu(dinv_i*(sum_{j->i} hs_j + hs_i) + b)     (warp per node, float4 lanes,
//                                                      4 edges in flight)
// hs_out_i = (x_i @ Wn) * dinv_i                       (shfl matvec)
__global__ __launch_bounds__(256) void aggA_kernel(
    const float* __restrict__ hs_in, float* __restrict__ hs_out,
    const float* __restrict__ bias, const float* __restrict__ Wn) {
    __shared__ float sW[32 * 33];
    __shared__ float sb[32];
    int tid = threadIdx.x;
    for (int i = tid; i < 1024; i += 256) sW[(i >> 5) * 33 + (i & 31)] = Wn[i];
    if (tid < 32) sb[tid] = bias[tid];
    __syncthreads();

    int node = (blockIdx.x * 256 + tid) >> 5;
    int lane = tid & 31;
    int slot = lane >> 3;          // 0..3 edge slots
    int cg = (lane & 7) << 2;      // col group 0,4,...,28
    int r0 = g_rowstart[node];
    int r1 = g_rowstart[node + 1];
    float4 acc = make_float4(0.f, 0.f, 0.f, 0.f);
    int e = r0;
    for (; e + 32 <= r1; e += 32) {
        int idx = g_csr[e + lane];
        #pragma unroll
        for (int j = 0; j < 8; j++) {
            int s = __shfl_sync(0xffffffffu, idx, slot * 8 + j);
            float4 v = *(const float4*)&hs_in[(size_t)s * HID + cg];
            acc.x += v.x; acc.y += v.y; acc.z += v.z; acc.w += v.w;
        }
    }
    int rem = r1 - e;
    if (rem) {
        int idx = (lane < rem) ? g_csr[e + lane] : 0;
        #pragma unroll
        for (int j = 0; j < 8; j++) {
            int t = slot * 8 + j;
            int s = __shfl_sync(0xffffffffu, idx, t);
            if (t < rem) {
                float4 v = *(const float4*)&hs_in[(size_t)s * HID + cg];
                acc.x += v.x; acc.y += v.y; acc.z += v.z; acc.w += v.w;
            }
        }
    }
    #pragma unroll
    for (int o = 8; o < 32; o <<= 1) {
        acc.x += __shfl_xor_sync(0xffffffffu, acc.x, o);
        acc.y += __shfl_xor_sync(0xffffffffu, acc.y, o);
        acc.z += __shfl_xor_sync(0xffffffffu, acc.z, o);
        acc.w += __shfl_xor_sync(0xffffffffu, acc.w, o);
    }
    float4 self = *(const float4*)&hs_in[(size_t)node * HID + cg];
    float dv = g_dinv[node];
    float4 x;
    x.x = fmaxf(dv * (acc.x + self.x) + sb[cg + 0], 0.f);
    x.y = fmaxf(dv * (acc.y + self.y) + sb[cg + 1], 0.f);
    x.z = fmaxf(dv * (acc.z + self.z) + sb[cg + 2], 0.f);
    x.w = fmaxf(dv * (acc.w + self.w) + sb[cg + 3], 0.f);
    // next linear: lane computes output col = lane
    float a2 = 0.f;
    #pragma unroll
    for (int q = 0; q < 8; q++) {
        float tx_ = __shfl_sync(0xffffffffu, x.x, q);
        float ty_ = __shfl_sync(0xffffffffu, x.y, q);
        float tz_ = __shfl_sync(0xffffffffu, x.z, q);
        float tw_ = __shfl_sync(0xffffffffu, x.w, q);
        a2 = fmaf(tx_, sW[(4 * q + 0) * 33 + lane], a2);
        a2 = fmaf(ty_, sW[(4 * q + 1) * 33 + lane], a2);
        a2 = fmaf(tz_, sW[(4 * q + 2) * 33 + lane], a2);
        a2 = fmaf(tw_, sW[(4 * q + 3) * 33 + lane], a2);
    }
    hs_out[(size_t)node * HID + lane] = a2 * dv;
}

// layer-3 aggregate fused with the MLP head -> writes final [NN,10] output
__global__ __launch_bounds__(256) void aggB_kernel(
    const float* __restrict__ hs_in, float* __restrict__ out,
    const float* __restrict__ bias,
    const float* __restrict__ l1W, const float* __restrict__ l1b,
    const float* __restrict__ l2W, const float* __restrict__ l2b) {
    __shared__ float sW1[32 * 16];
    __shared__ float sW2[16 * 10];
    __shared__ float sb[32], sb1[16], sb2[10];
    int tid = threadIdx.x;
    for (int i = tid; i < 512; i += 256) sW1[i] = l1W[i];
    if (tid < 160) sW2[tid] = l2W[tid];
    if (tid < 32)  sb[tid] = bias[tid];
    if (tid < 16)  sb1[tid] = l1b[tid];
    if (tid < 10)  sb2[tid] = l2b[tid];
    __syncthreads();

    int node = (blockIdx.x * 256 + tid) >> 5;
    int lane = tid & 31;
    int slot = lane >> 3;
    int cg = (lane & 7) << 2;
    int r0 = g_rowstart[node];
    int r1 = g_rowstart[node + 1];
    float4 acc = make_float4(0.f, 0.f, 0.f, 0.f);
    int e = r0;
    for (; e + 32 <= r1; e += 32) {
        int idx = g_csr[e + lane];
        #pragma unroll
        for (int j = 0; j < 8; j++) {
            int s = __shfl_sync(0xffffffffu, idx, slot * 8 + j);
            float4 v = *(const float4*)&hs_in[(size_t)s * HID + cg];
            acc.x += v.x; acc.y += v.y; acc.z += v.z; acc.w += v.w;
        }
    }
    int rem = r1 - e;
    if (rem) {
        int idx = (lane < rem) ? g_csr[e + lane] : 0;
        #pragma unroll
        for (int j = 0; j < 8; j++) {
            int t = slot * 8 + j;
            int s = __shfl_sync(0xffffffffu, idx, t);
            if (t < rem) {
                float4 v = *(const float4*)&hs_in[(size_t)s * HID + cg];
                acc.x += v.x; acc.y += v.y; acc.z += v.z; acc.w += v.w;
            }
        }
    }
    #pragma unroll
    for (int o = 8; o < 32; o <<= 1) {
        acc.x += __shfl_xor_sync(0xffffffffu, acc.x, o);
        acc.y += __shfl_xor_sync(0xffffffffu, acc.y, o);
        acc.z += __shfl_xor_sync(0xffffffffu, acc.z, o);
        acc.w += __shfl_xor_sync(0xffffffffu, acc.w, o);
    }
    float4 self = *(const float4*)&hs_in[(size_t)node * HID + cg];
    float dv = g_dinv[node];
    float4 x;
    x.x = fmaxf(dv * (acc.x + self.x) + sb[cg + 0], 0.f);
    x.y = fmaxf(dv * (acc.y + self.y) + sb[cg + 1], 0.f);
    x.z = fmaxf(dv * (acc.z + self.z) + sb[cg + 2], 0.f);
    x.w = fmaxf(dv * (acc.w + self.w) + sb[cg + 3], 0.f);
    // head layer 1: col c = lane&15 (lanes 16..31 duplicate)
    int c = lane & 15;
    float t1 = sb1[c];
    #pragma unroll
    for (int q = 0; q < 8; q++) {
        float tx_ = __shfl_sync(0xffffffffu, x.x, q);
        float ty_ = __shfl_sync(0xffffffffu, x.y, q);
        float tz_ = __shfl_sync(0xffffffffu, x.z, q);
        float tw_ = __shfl_sync(0xffffffffu, x.w, q);
        t1 = fmaf(tx_, sW1[(4 * q + 0) * 16 + c], t1);
        t1 = fmaf(ty_, sW1[(4 * q + 1) * 16 + c], t1);
        t1 = fmaf(tz_, sW1[(4 * q + 2) * 16 + c], t1);
        t1 = fmaf(tw_, sW1[(4 * q + 3) * 16 + c], t1);
    }
    t1 = fmaxf(t1, 0.f);
    // head layer 2: 10 outputs
    int oc = (lane < 10) ? lane : 0;
    float o = sb2[oc];
    #pragma unroll
    for (int c2 = 0; c2 < 16; c2++) {
        float tv = __shfl_sync(0xffffffffu, t1, c2);
        o = fmaf(tv, sW2[c2 * 10 + oc], o);
    }
    if (lane < 10) out[(size_t)node * 10 + lane] = o;
}

// ---------------- launch ----------------

extern "C" void kernel_launch(void* const* d_in, const int* in_sizes, int n_in,
                              void* d_out, int out_size) {
    (void)in_sizes; (void)n_in; (void)out_size;
    const float* x0   = (const float*)d_in[0];
    const int*   edge = (const int*)d_in[1];   // int32 (JAX x64 disabled)
    const float* W1  = (const float*)d_in[3];
    const float* b1  = (const float*)d_in[4];
    const float* W2  = (const float*)d_in[5];
    const float* b2  = (const float*)d_in[6];
    const float* W3  = (const float*)d_in[7];
    const float* b3  = (const float*)d_in[8];
    const float* l1W = (const float*)d_in[9];
    const float* l1b = (const float*)d_in[10];
    const float* l2W = (const float*)d_in[11];
    const float* l2b = (const float*)d_in[12];
    float* out = (float*)d_out;

    float* hsA; cudaGetSymbolAddress((void**)&hsA, g_hsA);
    float* hsB; cudaGetSymbolAddress((void**)&hsB, g_hsB);

    // CSR build
    zero_deg_kernel<<<(NN + 255) / 256, 256>>>();
    deg_kernel<<<(NE / 4 + 255) / 256, 256>>>(edge);
    scan1_kernel<<<NBLK_SCAN, 256>>>();
    scan2_kernel<<<1, 128>>>();
    scan3_kernel<<<NBLK_SCAN, 256>>>();
    scatter_kernel<<<(NE / 4 + 255) / 256, 256>>>(edge);

    // layer 1 (dense) -> hsA
    gemm1_kernel<<<(NN + 63) / 64, 128>>>(x0, W1);
    // agg1 + W2 linear -> hsB ; agg2 + W3 linear -> hsA ; agg3 + MLP head -> out
    aggA_kernel<<<12500, 256>>>(hsA, hsB, b1, W2);
    aggA_kernel<<<12500, 256>>>(hsB, hsA, b2, W3);
    aggB_kernel<<<12500, 256>>>(hsA, out, b3, l1W, l1b, l2W, l2b);
}